// round 8
// baseline (speedup 1.0000x reference)
#include <cuda_runtime.h>
#include <math.h>
#include <stdint.h>

// Problem shape (fixed by the dataset)
#define BB 16
#define NN 8192
#define DD 128
#define HH 64
#define EE 64
#define EPS_LN 1e-5f

#define BLK1 64               // blocks per batch in pass 1
#define ROWS1 (NN / BLK1)     // 128 rows per pass-1 block
#define TILE 128              // rows per pass-3 tile
#define XSP 132               // padded smem row stride (words)

// ---------------- scratch (__device__ globals; no allocation allowed) -------
__device__ float  d_partial[BB][BLK1][DD];  // per-block column sums of (x-mu)*rstd
__device__ float2 d_stats[BB * NN];         // per-row {mu, rstd}
__device__ float  d_Gt[BB][EE * DD];        // G^T: [e][d], G = diag(ln_w) Wr diag(lm) Wo
__device__ float  d_u[BB][EE];              // u = (ln_w@Wr ⊙ lm) @ Wo
__device__ float  d_h[BB][EE];              // h = (ln_b@Wr ⊙ lm) @ Wo + c

__device__ __forceinline__ uint32_t smem_u32(const void* p) {
    uint32_t a;
    asm("{ .reg .u64 t; cvta.to.shared.u64 t, %1; cvt.u32.u64 %0, t; }" : "=r"(a) : "l"(p));
    return a;
}
__device__ __forceinline__ uint32_t f2tf32(float v) {
    uint32_t r;
    asm("cvt.rna.tf32.f32 %0, %1;" : "=r"(r) : "f"(v));
    return r;
}
__device__ __forceinline__ void mma_tf32(float* c, const uint32_t* a,
                                         uint32_t b0, uint32_t b1) {
    asm volatile(
        "mma.sync.aligned.m16n8k8.row.col.f32.tf32.tf32.f32 "
        "{%0,%1,%2,%3}, {%4,%5,%6,%7}, {%8,%9}, {%0,%1,%2,%3};"
        : "+f"(c[0]), "+f"(c[1]), "+f"(c[2]), "+f"(c[3])
        : "r"(a[0]), "r"(a[1]), "r"(a[2]), "r"(a[3]), "r"(b0), "r"(b1));
}

// ============================ Pass 1: row stats + column sums ===============
// cp.async-staged: 64KB of x per block lands in smem with MLP=16/thread,
// then stats + normalized column sums are computed from smem.
#define K1_SMEM_WORDS (ROWS1 * XSP + 32 * DD)

__global__ void __launch_bounds__(256, 2) k1_stats(const float* __restrict__ x) {
    extern __shared__ float k1sm[];
    float* xs   = k1sm;                 // [ROWS1][XSP]
    float* sred = k1sm + ROWS1 * XSP;   // [32][DD]

    int b    = blockIdx.y;
    int tid  = threadIdx.x;
    int w    = tid >> 5;
    int lane = tid & 31;
    int rp   = lane >> 3;     // row within 4-row group
    int c    = lane & 7;      // float4 column chunk
    int rowbase = blockIdx.x * ROWS1 + w * 16;

    // ---- stage 64KB via cp.async (16 chunks/thread) ----
    {
        const char* src = (const char*)(x + ((size_t)b * NN + blockIdx.x * ROWS1) * DD);
        #pragma unroll
        for (int i = 0; i < 16; i++) {
            int fid = tid + i * 256;          // 4096 16B chunks
            int r = fid >> 5, cq = fid & 31;
            uint32_t dst = smem_u32(&xs[r * XSP + 4 * cq]);
            asm volatile("cp.async.cg.shared.global [%0], [%1], 16;"
                         :: "r"(dst), "l"(src + (size_t)fid * 16) : "memory");
        }
        asm volatile("cp.async.commit_group;" ::: "memory");
        asm volatile("cp.async.wait_group 0;" ::: "memory");
    }
    __syncthreads();

    float4 acc[4];
    #pragma unroll
    for (int j = 0; j < 4; j++) acc[j] = make_float4(0.f, 0.f, 0.f, 0.f);

    #pragma unroll
    for (int it = 0; it < 4; it++) {
        int rloc = w * 16 + it * 4 + rp;
        const float* xr = &xs[rloc * XSP];
        float4 v[4];
        #pragma unroll
        for (int j = 0; j < 4; j++)
            v[j] = *(const float4*)(xr + 4 * (c + 8 * j));
        float s = 0.f, q = 0.f;
        #pragma unroll
        for (int j = 0; j < 4; j++) {
            s += v[j].x + v[j].y + v[j].z + v[j].w;
            q += v[j].x * v[j].x + v[j].y * v[j].y + v[j].z * v[j].z + v[j].w * v[j].w;
        }
        #pragma unroll
        for (int o = 4; o > 0; o >>= 1) {
            s += __shfl_xor_sync(0xffffffffu, s, o);
            q += __shfl_xor_sync(0xffffffffu, q, o);
        }
        float mu   = s * (1.0f / DD);
        float rstd = rsqrtf(q * (1.0f / DD) - mu * mu + EPS_LN);
        if (c == 0) d_stats[b * NN + rowbase + it * 4 + rp] = make_float2(mu, rstd);
        #pragma unroll
        for (int j = 0; j < 4; j++) {
            acc[j].x += (v[j].x - mu) * rstd;
            acc[j].y += (v[j].y - mu) * rstd;
            acc[j].z += (v[j].z - mu) * rstd;
            acc[j].w += (v[j].w - mu) * rstd;
        }
    }
    __syncthreads();   // xs reads done before sred overlaps? (separate region; just order)

    {
        float4* dst = (float4*)&sred[(w * 4 + rp) * DD];
        #pragma unroll
        for (int j = 0; j < 4; j++) dst[c + 8 * j] = acc[j];
    }
    __syncthreads();
    if (tid < DD) {
        float s = 0.f;
        #pragma unroll
        for (int k = 0; k < 32; k++) s += sred[k * DD + tid];
        d_partial[b][blockIdx.x][tid] = s;
    }
}

// ============================ Pass 2: fold (one kernel, 128 blocks) ==========
__global__ void __launch_bounds__(256) k2_fold(
    const float* __restrict__ ln_w, const float* __restrict__ ln_b,
    const float* __restrict__ Wl,   const float* __restrict__ bl,
    const float* __restrict__ Wr,   const float* __restrict__ br,
    const float* __restrict__ Wo,   const float* __restrict__ bo) {
    __shared__ float sxa[2][DD];
    __shared__ float sx[DD];
    __shared__ float sr4[4][HH];
    __shared__ float slm[HH];
    __shared__ float sP[HH * EE];
    __shared__ float sWr[16 * HH];
    __shared__ float swv4[4][HH], sbv4[4][HH];

    int b = blockIdx.y, bx = blockIdx.x, tid = threadIdx.x;
    int d0 = bx * 16;

    {
        int col = tid & 127, hf = tid >> 7;
        float s = 0.f;
        #pragma unroll 8
        for (int p = hf * 32; p < hf * 32 + 32; p++) s += d_partial[b][p][col];
        sxa[hf][col] = s;
    }
    #pragma unroll
    for (int i = tid; i < 16 * HH; i += 256)
        sWr[i] = Wr[(d0 + (i >> 6)) * HH + (i & 63)];
    __syncthreads();
    if (tid < DD)
        sx[tid] = ln_w[tid] * ((sxa[0][tid] + sxa[1][tid]) * (1.0f / NN)) + ln_b[tid];
    __syncthreads();

    {
        int h = tid & 63, q = tid >> 6;
        float a = 0.f;
        #pragma unroll 8
        for (int d = q * 32; d < q * 32 + 32; d++) a += sx[d] * Wl[d * HH + h];
        sr4[q][h] = a;
    }
    __syncthreads();
    if (tid < HH)
        slm[tid] = bl[tid] + sr4[0][tid] + sr4[1][tid] + sr4[2][tid] + sr4[3][tid];
    __syncthreads();

    #pragma unroll
    for (int i = tid; i < HH * EE; i += 256) sP[i] = slm[i >> 6] * Wo[i];
    __syncthreads();

    // G rows -> write TRANSPOSED into d_Gt[b][e*DD + d]
    {
        int d_l = tid >> 4, e0 = (tid & 15) * 4;
        float a0 = 0.f, a1 = 0.f, a2 = 0.f, a3 = 0.f;
        #pragma unroll 8
        for (int h = 0; h < HH; h++) {
            float wv = sWr[d_l * HH + h];
            const float* p = &sP[h * EE + e0];
            a0 += wv * p[0]; a1 += wv * p[1]; a2 += wv * p[2]; a3 += wv * p[3];
        }
        int d = d0 + d_l;
        float lw = ln_w[d];
        float* gt = d_Gt[b];
        gt[(e0 + 0) * DD + d] = lw * a0;
        gt[(e0 + 1) * DD + d] = lw * a1;
        gt[(e0 + 2) * DD + d] = lw * a2;
        gt[(e0 + 3) * DD + d] = lw * a3;
    }

    if (bx == 0) {
        {
            int h = tid & 63, q = tid >> 6;
            float aw = 0.f, ab = 0.f;
            #pragma unroll 8
            for (int d = q * 32; d < q * 32 + 32; d++) {
                float wr = Wr[d * HH + h];
                aw += ln_w[d] * wr;
                ab += ln_b[d] * wr;
            }
            swv4[q][h] = aw; sbv4[q][h] = ab;
        }
        __syncthreads();
        if (tid < EE) {
            int e = tid;
            float su = 0.f, sh = 0.f, sc = bo[e];
            #pragma unroll 8
            for (int h = 0; h < HH; h++) {
                float p  = sP[h * EE + e];
                float wv = swv4[0][h] + swv4[1][h] + swv4[2][h] + swv4[3][h];
                float bv = sbv4[0][h] + sbv4[1][h] + sbv4[2][h] + sbv4[3][h];
                su += wv * p;
                sh += bv * p;
                sc += br[h] * p;
            }
            d_u[b][e] = su;
            d_h[b][e] = sh + sc;
        }
    }
}

// ============================ Pass 3: mma.sync tf32 GEMM =====================
// D[128,64] = X_tile[128,128] @ G[128,64]; epilogue rstd*(D - mu*u) + h.
// 256 threads / 8 warps; warp w owns rows [16w, 16w+16), all 64 cols.
#define K3_SMEM_WORDS (TILE * XSP /*X tf32*/ + EE * XSP /*Gt tf32*/ + EE + EE + 2 * TILE)

__global__ void __launch_bounds__(256, 2) k3_mma(const float* __restrict__ x,
                                                 float* __restrict__ out) {
    extern __shared__ uint32_t sm[];
    uint32_t* Xs  = sm;                       // [TILE][XSP] tf32 bits
    uint32_t* Gts = Xs + TILE * XSP;          // [EE][XSP]  tf32 bits of G^T
    float*    su  = (float*)(Gts + EE * XSP); // [EE]
    float*    sh  = su + EE;                  // [EE]
    float2*   sst = (float2*)(sh + EE);       // [TILE] {mu, rstd}

    int b    = blockIdx.y;
    int tid  = threadIdx.x;
    int w    = tid >> 5, lane = tid & 31;
    int g    = lane >> 2, t = lane & 3;       // fragment group / in-group id
    int row0 = blockIdx.x * TILE;

    // ---- stage X (tf32): 16 chunks/thread ----
    {
        const float4* xb = (const float4*)(x + ((size_t)b * NN + row0) * DD);
        #pragma unroll
        for (int i = 0; i < 16; i++) {
            int fid = tid + i * 256;          // 4096 float4 chunks
            int r = fid >> 5, cq = fid & 31;
            float4 v = xb[fid];
            uint4 tv = make_uint4(f2tf32(v.x), f2tf32(v.y), f2tf32(v.z), f2tf32(v.w));
            *(uint4*)&Xs[r * XSP + 4 * cq] = tv;
        }
    }
    // ---- stage G^T (tf32): 8 chunks/thread ----
    {
        const float4* gt = (const float4*)d_Gt[b];
        #pragma unroll
        for (int i = 0; i < 8; i++) {
            int fid = tid + i * 256;          // 2048 chunks
            int e = fid >> 5, cq = fid & 31;
            float4 v = gt[fid];
            uint4 tv = make_uint4(f2tf32(v.x), f2tf32(v.y), f2tf32(v.z), f2tf32(v.w));
            *(uint4*)&Gts[e * XSP + 4 * cq] = tv;
        }
    }
    if (tid < EE) { su[tid] = d_u[b][tid]; sh[tid] = d_h[b][tid]; }
    if (tid < TILE) sst[tid] = d_stats[b * NN + row0 + tid];
    __syncthreads();

    // ---- mainloop: 16 k-steps, 8 HMMA each ----
    float acc[8][4];
    #pragma unroll
    for (int nt = 0; nt < 8; nt++)
        #pragma unroll
        for (int j = 0; j < 4; j++) acc[nt][j] = 0.f;

    int rA0 = w * 16 + g;        // rows rA0, rA0+8
    #pragma unroll
    for (int ks = 0; ks < 16; ks++) {
        int k0 = ks * 8;
        uint32_t a[4];
        {
            const uint32_t* xr = &Xs[rA0 * XSP + k0 + t];
            a[0] = xr[0];
            a[1] = xr[8 * XSP];
            a[2] = xr[4];
            a[3] = xr[8 * XSP + 4];
        }
        #pragma unroll
        for (int nt = 0; nt < 8; nt++) {
            const uint32_t* gr = &Gts[(nt * 8 + g) * XSP + k0 + t];
            mma_tf32(acc[nt], a, gr[0], gr[4]);
        }
    }

    // ---- epilogue: out = rstd*(acc - mu*u) + h ----
    {
        int rl = w * 16 + g;                  // local rows rl, rl+8
        float2 st0 = sst[rl];
        float2 st8 = sst[rl + 8];
        size_t ob0 = ((size_t)b * NN + row0 + rl) * EE;
        size_t ob8 = ob0 + 8 * EE;
        #pragma unroll
        for (int nt = 0; nt < 8; nt++) {
            int c = nt * 8 + t * 2;
            float2 uv = *(float2*)&su[c];
            float2 hv = *(float2*)&sh[c];
            float2 o0, o8;
            o0.x = st0.y * (acc[nt][0] - st0.x * uv.x) + hv.x;
            o0.y = st0.y * (acc[nt][1] - st0.x * uv.y) + hv.y;
            o8.x = st8.y * (acc[nt][2] - st8.x * uv.x) + hv.x;
            o8.y = st8.y * (acc[nt][3] - st8.x * uv.y) + hv.y;
            *(float2*)&out[ob0 + c] = o0;
            *(float2*)&out[ob8 + c] = o8;
        }
    }
}

// ============================ launch =========================================
extern "C" void kernel_launch(void* const* d_in, const int* in_sizes, int n_in,
                              void* d_out, int out_size) {
    const float* x    = (const float*)d_in[0];
    const float* ln_w = (const float*)d_in[1];
    const float* ln_b = (const float*)d_in[2];
    const float* Wl   = (const float*)d_in[3];
    const float* bl   = (const float*)d_in[4];
    const float* Wr   = (const float*)d_in[5];
    const float* br   = (const float*)d_in[6];
    const float* Wo   = (const float*)d_in[7];
    const float* bo   = (const float*)d_in[8];
    float* out = (float*)d_out;

    const int k1_smem = K1_SMEM_WORDS * (int)sizeof(float);
    const int k3_smem = K3_SMEM_WORDS * (int)sizeof(uint32_t);
    cudaFuncSetAttribute(k1_stats, cudaFuncAttributeMaxDynamicSharedMemorySize, k1_smem);
    cudaFuncSetAttribute(k3_mma, cudaFuncAttributeMaxDynamicSharedMemorySize, k3_smem);

    k1_stats<<<dim3(BLK1, BB), 256, k1_smem>>>(x);
    k2_fold<<<dim3(8, BB), 256>>>(ln_w, ln_b, Wl, bl, Wr, br, Wo, bo);
    k3_mma<<<dim3(NN / TILE, BB), 256, k3_smem>>>(x, out);
}

// round 9
// speedup vs baseline: 1.1244x; 1.1244x over previous
#include <cuda_runtime.h>
#include <math.h>
#include <stdint.h>

// Problem shape (fixed by the dataset)
#define BB 16
#define NN 8192
#define DD 128
#define HH 64
#define EE 64
#define EPS_LN 1e-5f

#define BLK1 128              // blocks per batch in pass 1
#define ROWS1 (NN / BLK1)     // 64 rows per pass-1 block
#define TILE 128              // rows per pass-3 tile
#define XSP 132               // padded smem row stride (words)

// ---------------- scratch (__device__ globals; no allocation allowed) -------
__device__ float  d_partial[BB][BLK1][DD];  // per-block column sums of (x-mu)*rstd
__device__ float2 d_stats[BB * NN];         // per-row {mu, rstd}
__device__ float  d_Gt[BB][EE * DD];        // G^T: [e][d], G = diag(ln_w) Wr diag(lm) Wo
__device__ float  d_u[BB][EE];              // u = (ln_w@Wr ⊙ lm) @ Wo
__device__ float  d_h[BB][EE];              // h = (ln_b@Wr ⊙ lm) @ Wo + c

__device__ __forceinline__ uint32_t f2tf32(float v) {
    uint32_t r;
    asm("cvt.rna.tf32.f32 %0, %1;" : "=r"(r) : "f"(v));
    return r;
}
__device__ __forceinline__ void mma_tf32(float* c, const uint32_t* a,
                                         uint32_t b0, uint32_t b1) {
    asm volatile(
        "mma.sync.aligned.m16n8k8.row.col.f32.tf32.tf32.f32 "
        "{%0,%1,%2,%3}, {%4,%5,%6,%7}, {%8,%9}, {%0,%1,%2,%3};"
        : "+f"(c[0]), "+f"(c[1]), "+f"(c[2]), "+f"(c[3])
        : "r"(a[0]), "r"(a[1]), "r"(a[2]), "r"(a[3]), "r"(b0), "r"(b1));
}

// ============================ Pass 1: row stats + column sums ===============
// 8 lanes per row; 3-round butterfly; 64 rows per block (2 iterations/warp).
__global__ void k1_stats(const float* __restrict__ x) {
    int b    = blockIdx.y;
    int w    = threadIdx.x >> 5;
    int lane = threadIdx.x & 31;
    int rp   = lane >> 3;     // row within 4-row group
    int c    = lane & 7;      // float4 column chunk
    int rowbase = blockIdx.x * ROWS1 + w * (ROWS1 / 8);   // 8 rows per warp

    const float4* xb = (const float4*)(x + (size_t)b * NN * DD);

    float4 acc[4];
    #pragma unroll
    for (int j = 0; j < 4; j++) acc[j] = make_float4(0.f, 0.f, 0.f, 0.f);

    #pragma unroll
    for (int it = 0; it < ROWS1 / 32; it++) {
        int row = rowbase + it * 4 + rp;
        float4 v[4];
        #pragma unroll
        for (int j = 0; j < 4; j++)
            v[j] = xb[row * (DD / 4) + (c + 8 * j)];
        float s = 0.f, q = 0.f;
        #pragma unroll
        for (int j = 0; j < 4; j++) {
            s += v[j].x + v[j].y + v[j].z + v[j].w;
            q += v[j].x * v[j].x + v[j].y * v[j].y + v[j].z * v[j].z + v[j].w * v[j].w;
        }
        #pragma unroll
        for (int o = 4; o > 0; o >>= 1) {
            s += __shfl_xor_sync(0xffffffffu, s, o);
            q += __shfl_xor_sync(0xffffffffu, q, o);
        }
        float mu   = s * (1.0f / DD);
        float rstd = rsqrtf(q * (1.0f / DD) - mu * mu + EPS_LN);
        if (c == 0) d_stats[b * NN + row] = make_float2(mu, rstd);
        #pragma unroll
        for (int j = 0; j < 4; j++) {
            acc[j].x += (v[j].x - mu) * rstd;
            acc[j].y += (v[j].y - mu) * rstd;
            acc[j].z += (v[j].z - mu) * rstd;
            acc[j].w += (v[j].w - mu) * rstd;
        }
    }

    __shared__ float sred[32][DD];
    {
        float4* dst = (float4*)sred[w * 4 + rp];
        #pragma unroll
        for (int j = 0; j < 4; j++) dst[c + 8 * j] = acc[j];
    }
    __syncthreads();
    if (threadIdx.x < DD) {
        float s = 0.f;
        #pragma unroll
        for (int k = 0; k < 32; k++) s += sred[k][threadIdx.x];
        d_partial[b][blockIdx.x][threadIdx.x] = s;
    }
}

// ============================ Pass 2: fold (one kernel, 128 blocks) ==========
__global__ void __launch_bounds__(256) k2_fold(
    const float* __restrict__ ln_w, const float* __restrict__ ln_b,
    const float* __restrict__ Wl,   const float* __restrict__ bl,
    const float* __restrict__ Wr,   const float* __restrict__ br,
    const float* __restrict__ Wo,   const float* __restrict__ bo) {
    __shared__ float sxa[2][DD];
    __shared__ float sx[DD];
    __shared__ float sr4[4][HH];
    __shared__ float slm[HH];
    __shared__ float sP[HH * EE];
    __shared__ float sWr[16 * HH];
    __shared__ float swv4[4][HH], sbv4[4][HH];

    int b = blockIdx.y, bx = blockIdx.x, tid = threadIdx.x;
    int d0 = bx * 16;

    {
        int col = tid & 127, hf = tid >> 7;
        float s = 0.f;
        #pragma unroll 8
        for (int p = hf * (BLK1 / 2); p < (hf + 1) * (BLK1 / 2); p++)
            s += d_partial[b][p][col];
        sxa[hf][col] = s;
    }
    #pragma unroll
    for (int i = tid; i < 16 * HH; i += 256)
        sWr[i] = Wr[(d0 + (i >> 6)) * HH + (i & 63)];
    __syncthreads();
    if (tid < DD)
        sx[tid] = ln_w[tid] * ((sxa[0][tid] + sxa[1][tid]) * (1.0f / NN)) + ln_b[tid];
    __syncthreads();

    {
        int h = tid & 63, q = tid >> 6;
        float a = 0.f;
        #pragma unroll 8
        for (int d = q * 32; d < q * 32 + 32; d++) a += sx[d] * Wl[d * HH + h];
        sr4[q][h] = a;
    }
    __syncthreads();
    if (tid < HH)
        slm[tid] = bl[tid] + sr4[0][tid] + sr4[1][tid] + sr4[2][tid] + sr4[3][tid];
    __syncthreads();

    #pragma unroll
    for (int i = tid; i < HH * EE; i += 256) sP[i] = slm[i >> 6] * Wo[i];
    __syncthreads();

    // G rows -> write TRANSPOSED into d_Gt[b][e*DD + d]
    {
        int d_l = tid >> 4, e0 = (tid & 15) * 4;
        float a0 = 0.f, a1 = 0.f, a2 = 0.f, a3 = 0.f;
        #pragma unroll 8
        for (int h = 0; h < HH; h++) {
            float wv = sWr[d_l * HH + h];
            const float* p = &sP[h * EE + e0];
            a0 += wv * p[0]; a1 += wv * p[1]; a2 += wv * p[2]; a3 += wv * p[3];
        }
        int d = d0 + d_l;
        float lw = ln_w[d];
        float* gt = d_Gt[b];
        gt[(e0 + 0) * DD + d] = lw * a0;
        gt[(e0 + 1) * DD + d] = lw * a1;
        gt[(e0 + 2) * DD + d] = lw * a2;
        gt[(e0 + 3) * DD + d] = lw * a3;
    }

    if (bx == 0) {
        {
            int h = tid & 63, q = tid >> 6;
            float aw = 0.f, ab = 0.f;
            #pragma unroll 8
            for (int d = q * 32; d < q * 32 + 32; d++) {
                float wr = Wr[d * HH + h];
                aw += ln_w[d] * wr;
                ab += ln_b[d] * wr;
            }
            swv4[q][h] = aw; sbv4[q][h] = ab;
        }
        __syncthreads();
        if (tid < EE) {
            int e = tid;
            float su = 0.f, sh = 0.f, sc = bo[e];
            #pragma unroll 8
            for (int h = 0; h < HH; h++) {
                float p  = sP[h * EE + e];
                float wv = swv4[0][h] + swv4[1][h] + swv4[2][h] + swv4[3][h];
                float bv = sbv4[0][h] + sbv4[1][h] + sbv4[2][h] + sbv4[3][h];
                su += wv * p;
                sh += bv * p;
                sc += br[h] * p;
            }
            d_u[b][e] = su;
            d_h[b][e] = sh + sc;
        }
    }
}

// ============================ Pass 3: mma.sync tf32 GEMM =====================
// D[128,64] = X_tile[128,128] @ G[128,64]; epilogue rstd*(D - mu*u) + h.
// 128 threads / 4 warps; warp w owns rows [32w, 32w+32), all 64 cols.
// (Exact R7 configuration — measured fastest.)
#define K3_SMEM_WORDS (TILE * XSP /*X tf32*/ + EE * XSP /*Gt tf32*/ + EE + EE + 2 * TILE)

__global__ void __launch_bounds__(128, 2) k3_mma(const float* __restrict__ x,
                                                 float* __restrict__ out) {
    extern __shared__ uint32_t sm[];
    uint32_t* Xs  = sm;                       // [TILE][XSP] tf32 bits
    uint32_t* Gts = Xs + TILE * XSP;          // [EE][XSP]  tf32 bits of G^T
    float*    su  = (float*)(Gts + EE * XSP); // [EE]
    float*    sh  = su + EE;                  // [EE]
    float2*   sst = (float2*)(sh + EE);       // [TILE] {mu, rstd}

    int b    = blockIdx.y;
    int tid  = threadIdx.x;
    int w    = tid >> 5, lane = tid & 31;
    int g    = lane >> 2, t = lane & 3;       // fragment group / in-group id
    int row0 = blockIdx.x * TILE;

    // ---- stage X (tf32) ----
    {
        const float4* xb = (const float4*)(x + ((size_t)b * NN + row0) * DD);
        #pragma unroll
        for (int i = 0; i < 32; i++) {
            int fid = tid + i * 128;          // 4096 float4 chunks
            int r = fid >> 5, cq = fid & 31;
            float4 v = xb[fid];
            uint4 tv = make_uint4(f2tf32(v.x), f2tf32(v.y), f2tf32(v.z), f2tf32(v.w));
            *(uint4*)&Xs[r * XSP + 4 * cq] = tv;
        }
    }
    // ---- stage G^T (tf32) ----
    {
        const float4* gt = (const float4*)d_Gt[b];
        #pragma unroll
        for (int i = 0; i < 16; i++) {
            int fid = tid + i * 128;          // 2048 chunks
            int e = fid >> 5, cq = fid & 31;
            float4 v = gt[fid];
            uint4 tv = make_uint4(f2tf32(v.x), f2tf32(v.y), f2tf32(v.z), f2tf32(v.w));
            *(uint4*)&Gts[e * XSP + 4 * cq] = tv;
        }
    }
    if (tid < EE) { su[tid] = d_u[b][tid]; sh[tid] = d_h[b][tid]; }
    sst[tid] = d_stats[b * NN + row0 + tid];
    __syncthreads();

    // ---- mainloop: 16 k-steps, 16 HMMA each ----
    float acc[2][8][4];
    #pragma unroll
    for (int mt = 0; mt < 2; mt++)
        #pragma unroll
        for (int nt = 0; nt < 8; nt++)
            #pragma unroll
            for (int j = 0; j < 4; j++) acc[mt][nt][j] = 0.f;

    int rA0 = w * 32 + g;        // rows rA0, rA0+8 (mt=0); +16 for mt=1
    #pragma unroll
    for (int ks = 0; ks < 16; ks++) {
        int k0 = ks * 8;
        uint32_t a[2][4];
        #pragma unroll
        for (int mt = 0; mt < 2; mt++) {
            const uint32_t* xr = &Xs[(rA0 + mt * 16) * XSP + k0 + t];
            a[mt][0] = xr[0];
            a[mt][1] = xr[8 * XSP];
            a[mt][2] = xr[4];
            a[mt][3] = xr[8 * XSP + 4];
        }
        #pragma unroll
        for (int nt = 0; nt < 8; nt++) {
            const uint32_t* gr = &Gts[(nt * 8 + g) * XSP + k0 + t];
            uint32_t b0 = gr[0], b1 = gr[4];
            mma_tf32(acc[0][nt], a[0], b0, b1);
            mma_tf32(acc[1][nt], a[1], b0, b1);
        }
    }

    // ---- epilogue: out = rstd*(acc - mu*u) + h ----
    #pragma unroll
    for (int mt = 0; mt < 2; mt++) {
        int rl = w * 32 + mt * 16 + g;        // local rows rl, rl+8
        float2 st0 = sst[rl];
        float2 st8 = sst[rl + 8];
        size_t ob0 = ((size_t)b * NN + row0 + rl) * EE;
        size_t ob8 = ob0 + 8 * EE;
        #pragma unroll
        for (int nt = 0; nt < 8; nt++) {
            int c = nt * 8 + t * 2;
            float2 uv = *(float2*)&su[c];
            float2 hv = *(float2*)&sh[c];
            float2 o0, o8;
            o0.x = st0.y * (acc[mt][nt][0] - st0.x * uv.x) + hv.x;
            o0.y = st0.y * (acc[mt][nt][1] - st0.x * uv.y) + hv.y;
            o8.x = st8.y * (acc[mt][nt][2] - st8.x * uv.x) + hv.x;
            o8.y = st8.y * (acc[mt][nt][3] - st8.x * uv.y) + hv.y;
            *(float2*)&out[ob0 + c] = o0;
            *(float2*)&out[ob8 + c] = o8;
        }
    }
}

// ============================ launch =========================================
extern "C" void kernel_launch(void* const* d_in, const int* in_sizes, int n_in,
                              void* d_out, int out_size) {
    const float* x    = (const float*)d_in[0];
    const float* ln_w = (const float*)d_in[1];
    const float* ln_b = (const float*)d_in[2];
    const float* Wl   = (const float*)d_in[3];
    const float* bl   = (const float*)d_in[4];
    const float* Wr   = (const float*)d_in[5];
    const float* br   = (const float*)d_in[6];
    const float* Wo   = (const float*)d_in[7];
    const float* bo   = (const float*)d_in[8];
    float* out = (float*)d_out;

    const int k3_smem = K3_SMEM_WORDS * (int)sizeof(uint32_t);
    cudaFuncSetAttribute(k3_mma, cudaFuncAttributeMaxDynamicSharedMemorySize, k3_smem);

    k1_stats<<<dim3(BLK1, BB), 256>>>(x);
    k2_fold<<<dim3(8, BB), 256>>>(ln_w, ln_b, Wl, bl, Wr, br, Wo, bo);
    k3_mma<<<dim3(NN / TILE, BB), 128, k3_smem>>>(x, out);
}

// round 10
// speedup vs baseline: 1.1666x; 1.0375x over previous
#include <cuda_runtime.h>
#include <math.h>
#include <stdint.h>

// Problem shape (fixed by the dataset)
#define BB 16
#define NN 8192
#define DD 128
#define HH 64
#define EE 64
#define EPS_LN 1e-5f

#define BLK1 64               // blocks per batch in pass 1
#define ROWS1 (NN / BLK1)     // 128 rows per pass-1 block
#define TILE 64               // rows per pass-3 tile
#define NT 2                  // tiles per pass-3 block (double buffered)
#define XSP 132               // padded smem row stride (words)

// ---------------- scratch (__device__ globals; no allocation allowed) -------
__device__ float    d_partial[BB][BLK1][DD]; // per-block col sums of (x-mu)*rstd
__device__ float2   d_stats[BB * NN];        // per-row {mu, rstd}
__device__ uint32_t d_Gt[BB][EE * DD];       // G^T as tf32 bits: [e][d]
__device__ float    d_u[BB][EE];             // u = (ln_w@Wr ⊙ lm) @ Wo
__device__ float    d_h[BB][EE];             // h = (ln_b@Wr ⊙ lm) @ Wo + c

__device__ __forceinline__ uint32_t smem_u32(const void* p) {
    uint32_t a;
    asm("{ .reg .u64 t; cvta.to.shared.u64 t, %1; cvt.u32.u64 %0, t; }" : "=r"(a) : "l"(p));
    return a;
}
__device__ __forceinline__ uint32_t f2tf32(float v) {
    uint32_t r;
    asm("cvt.rna.tf32.f32 %0, %1;" : "=r"(r) : "f"(v));
    return r;
}
__device__ __forceinline__ void cp16(uint32_t dst, const void* src) {
    asm volatile("cp.async.cg.shared.global [%0], [%1], 16;"
                 :: "r"(dst), "l"(src) : "memory");
}
__device__ __forceinline__ void mma_tf32(float* c, const uint32_t* a,
                                         uint32_t b0, uint32_t b1) {
    asm volatile(
        "mma.sync.aligned.m16n8k8.row.col.f32.tf32.tf32.f32 "
        "{%0,%1,%2,%3}, {%4,%5,%6,%7}, {%8,%9}, {%0,%1,%2,%3};"
        : "+f"(c[0]), "+f"(c[1]), "+f"(c[2]), "+f"(c[3])
        : "r"(a[0]), "r"(a[1]), "r"(a[2]), "r"(a[3]), "r"(b0), "r"(b1));
}

// ============================ Pass 1: row stats + column sums ===============
// (exact R7 configuration — measured best)
__global__ void k1_stats(const float* __restrict__ x) {
    int b    = blockIdx.y;
    int w    = threadIdx.x >> 5;
    int lane = threadIdx.x & 31;
    int rp   = lane >> 3;
    int c    = lane & 7;
    int rowbase = blockIdx.x * ROWS1 + w * (ROWS1 / 8);

    const float4* xb = (const float4*)(x + (size_t)b * NN * DD);

    float4 acc[4];
    #pragma unroll
    for (int j = 0; j < 4; j++) acc[j] = make_float4(0.f, 0.f, 0.f, 0.f);

    #pragma unroll
    for (int it = 0; it < 4; it++) {
        int row = rowbase + it * 4 + rp;
        float4 v[4];
        #pragma unroll
        for (int j = 0; j < 4; j++)
            v[j] = xb[row * (DD / 4) + (c + 8 * j)];
        float s = 0.f, q = 0.f;
        #pragma unroll
        for (int j = 0; j < 4; j++) {
            s += v[j].x + v[j].y + v[j].z + v[j].w;
            q += v[j].x * v[j].x + v[j].y * v[j].y + v[j].z * v[j].z + v[j].w * v[j].w;
        }
        #pragma unroll
        for (int o = 4; o > 0; o >>= 1) {
            s += __shfl_xor_sync(0xffffffffu, s, o);
            q += __shfl_xor_sync(0xffffffffu, q, o);
        }
        float mu   = s * (1.0f / DD);
        float rstd = rsqrtf(q * (1.0f / DD) - mu * mu + EPS_LN);
        if (c == 0) d_stats[b * NN + row] = make_float2(mu, rstd);
        #pragma unroll
        for (int j = 0; j < 4; j++) {
            acc[j].x += (v[j].x - mu) * rstd;
            acc[j].y += (v[j].y - mu) * rstd;
            acc[j].z += (v[j].z - mu) * rstd;
            acc[j].w += (v[j].w - mu) * rstd;
        }
    }

    __shared__ float sred[32][DD];
    {
        float4* dst = (float4*)sred[w * 4 + rp];
        #pragma unroll
        for (int j = 0; j < 4; j++) dst[c + 8 * j] = acc[j];
    }
    __syncthreads();
    if (threadIdx.x < DD) {
        float s = 0.f;
        #pragma unroll
        for (int k = 0; k < 32; k++) s += sred[k][threadIdx.x];
        d_partial[b][blockIdx.x][threadIdx.x] = s;
    }
}

// ============================ Pass 2: fold (one kernel, 128 blocks) ==========
__global__ void __launch_bounds__(256) k2_fold(
    const float* __restrict__ ln_w, const float* __restrict__ ln_b,
    const float* __restrict__ Wl,   const float* __restrict__ bl,
    const float* __restrict__ Wr,   const float* __restrict__ br,
    const float* __restrict__ Wo,   const float* __restrict__ bo) {
    __shared__ float sxa[2][DD];
    __shared__ float sx[DD];
    __shared__ float sr4[4][HH];
    __shared__ float slm[HH];
    __shared__ float sP[HH * EE];
    __shared__ float sWr[16 * HH];
    __shared__ float swv4[4][HH], sbv4[4][HH];

    int b = blockIdx.y, bx = blockIdx.x, tid = threadIdx.x;
    int d0 = bx * 16;

    {
        int col = tid & 127, hf = tid >> 7;
        float s = 0.f;
        #pragma unroll 8
        for (int p = hf * 32; p < hf * 32 + 32; p++) s += d_partial[b][p][col];
        sxa[hf][col] = s;
    }
    #pragma unroll
    for (int i = tid; i < 16 * HH; i += 256)
        sWr[i] = Wr[(d0 + (i >> 6)) * HH + (i & 63)];
    __syncthreads();
    if (tid < DD)
        sx[tid] = ln_w[tid] * ((sxa[0][tid] + sxa[1][tid]) * (1.0f / NN)) + ln_b[tid];
    __syncthreads();

    {
        int h = tid & 63, q = tid >> 6;
        float a = 0.f;
        #pragma unroll 8
        for (int d = q * 32; d < q * 32 + 32; d++) a += sx[d] * Wl[d * HH + h];
        sr4[q][h] = a;
    }
    __syncthreads();
    if (tid < HH)
        slm[tid] = bl[tid] + sr4[0][tid] + sr4[1][tid] + sr4[2][tid] + sr4[3][tid];
    __syncthreads();

    #pragma unroll
    for (int i = tid; i < HH * EE; i += 256) sP[i] = slm[i >> 6] * Wo[i];
    __syncthreads();

    // G rows -> write TRANSPOSED tf32 bits into d_Gt[b][e*DD + d]
    {
        int d_l = tid >> 4, e0 = (tid & 15) * 4;
        float a0 = 0.f, a1 = 0.f, a2 = 0.f, a3 = 0.f;
        #pragma unroll 8
        for (int h = 0; h < HH; h++) {
            float wv = sWr[d_l * HH + h];
            const float* p = &sP[h * EE + e0];
            a0 += wv * p[0]; a1 += wv * p[1]; a2 += wv * p[2]; a3 += wv * p[3];
        }
        int d = d0 + d_l;
        float lw = ln_w[d];
        uint32_t* gt = d_Gt[b];
        gt[(e0 + 0) * DD + d] = f2tf32(lw * a0);
        gt[(e0 + 1) * DD + d] = f2tf32(lw * a1);
        gt[(e0 + 2) * DD + d] = f2tf32(lw * a2);
        gt[(e0 + 3) * DD + d] = f2tf32(lw * a3);
    }

    if (bx == 0) {
        {
            int h = tid & 63, q = tid >> 6;
            float aw = 0.f, ab = 0.f;
            #pragma unroll 8
            for (int d = q * 32; d < q * 32 + 32; d++) {
                float wr = Wr[d * HH + h];
                aw += ln_w[d] * wr;
                ab += ln_b[d] * wr;
            }
            swv4[q][h] = aw; sbv4[q][h] = ab;
        }
        __syncthreads();
        if (tid < EE) {
            int e = tid;
            float su = 0.f, sh = 0.f, sc = bo[e];
            #pragma unroll 8
            for (int h = 0; h < HH; h++) {
                float p  = sP[h * EE + e];
                float wv = swv4[0][h] + swv4[1][h] + swv4[2][h] + swv4[3][h];
                float bv = sbv4[0][h] + sbv4[1][h] + sbv4[2][h] + sbv4[3][h];
                su += wv * p;
                sh += bv * p;
                sc += br[h] * p;
            }
            d_u[b][e] = su;
            d_h[b][e] = sh + sc;
        }
    }
}

// ============================ Pass 3: pipelined mma.sync tf32 GEMM ===========
// Per block: Gt staged once (cp.async), NT=2 tiles of 64 rows with X double
// buffer. X staged raw fp32 via cp.async; converted to tf32 in registers at
// fragment-load time (full RNA precision). 4 warps; warp w owns 16 rows.
#define K3_SMEM_WORDS (EE * XSP + NT * TILE * XSP + EE + EE + 2 * (NT * TILE))

__global__ void __launch_bounds__(128, 2) k3_mma(const float* __restrict__ x,
                                                 float* __restrict__ out) {
    extern __shared__ uint32_t sm[];
    uint32_t* Gts = sm;                        // [EE][XSP] tf32 bits
    uint32_t* Xb  = Gts + EE * XSP;            // [2][TILE][XSP] raw fp32 bits
    float*    su  = (float*)(Xb + NT * TILE * XSP);
    float*    sh  = su + EE;
    float2*   sst = (float2*)(sh + EE);        // [NT*TILE]

    int b    = blockIdx.y;
    int tid  = threadIdx.x;
    int w    = tid >> 5, lane = tid & 31;
    int g    = lane >> 2, t = lane & 3;
    int rowblk = blockIdx.x * (NT * TILE);

    // ---- group 0: Gt + X tile 0 ----
    {
        const char* gsrc = (const char*)d_Gt[b];
        #pragma unroll
        for (int i = 0; i < 16; i++) {
            int fid = tid + i * 128;           // 2048 16B chunks
            int e = fid >> 5, cq = fid & 31;
            cp16(smem_u32(&Gts[e * XSP + 4 * cq]), gsrc + (size_t)fid * 16);
        }
        const char* xsrc = (const char*)(x + ((size_t)b * NN + rowblk) * DD);
        #pragma unroll
        for (int i = 0; i < 16; i++) {
            int fid = tid + i * 128;           // 2048 chunks (64 rows)
            int r = fid >> 5, cq = fid & 31;
            cp16(smem_u32(&Xb[r * XSP + 4 * cq]), xsrc + (size_t)fid * 16);
        }
        asm volatile("cp.async.commit_group;" ::: "memory");
    }
    // small operands via regular loads
    if (tid < EE) { su[tid] = d_u[b][tid]; sh[tid] = d_h[b][tid]; }
    sst[tid] = d_stats[b * NN + rowblk + tid];   // 128 rows, 128 threads

    #pragma unroll
    for (int tt = 0; tt < NT; tt++) {
        // prefetch next tile into the other buffer
        if (tt + 1 < NT) {
            const char* xsrc = (const char*)(x + ((size_t)b * NN + rowblk + (tt + 1) * TILE) * DD);
            uint32_t* dstb = Xb + ((tt + 1) & 1) * TILE * XSP;
            #pragma unroll
            for (int i = 0; i < 16; i++) {
                int fid = tid + i * 128;
                int r = fid >> 5, cq = fid & 31;
                cp16(smem_u32(&dstb[r * XSP + 4 * cq]), xsrc + (size_t)fid * 16);
            }
            asm volatile("cp.async.commit_group;" ::: "memory");
            asm volatile("cp.async.wait_group 1;" ::: "memory");
        } else {
            asm volatile("cp.async.wait_group 0;" ::: "memory");
        }
        __syncthreads();

        const uint32_t* Xs = Xb + (tt & 1) * TILE * XSP;

        // ---- mainloop: 16 k-steps, 8 HMMA each ----
        float acc[8][4];
        #pragma unroll
        for (int nt = 0; nt < 8; nt++)
            #pragma unroll
            for (int j = 0; j < 4; j++) acc[nt][j] = 0.f;

        int rA0 = w * 16 + g;
        #pragma unroll
        for (int ks = 0; ks < 16; ks++) {
            int k0 = ks * 8;
            uint32_t a[4];
            {
                const uint32_t* xr = &Xs[rA0 * XSP + k0 + t];
                a[0] = f2tf32(__uint_as_float(xr[0]));
                a[1] = f2tf32(__uint_as_float(xr[8 * XSP]));
                a[2] = f2tf32(__uint_as_float(xr[4]));
                a[3] = f2tf32(__uint_as_float(xr[8 * XSP + 4]));
            }
            #pragma unroll
            for (int nt = 0; nt < 8; nt++) {
                const uint32_t* gr = &Gts[(nt * 8 + g) * XSP + k0 + t];
                mma_tf32(acc[nt], a, gr[0], gr[4]);
            }
        }

        // ---- epilogue: out = rstd*(acc - mu*u) + h ----
        {
            int rl = tt * TILE + w * 16 + g;     // local rows rl, rl+8
            float2 st0 = sst[rl];
            float2 st8 = sst[rl + 8];
            size_t ob0 = ((size_t)b * NN + rowblk + rl) * EE;
            size_t ob8 = ob0 + 8 * EE;
            #pragma unroll
            for (int nt = 0; nt < 8; nt++) {
                int c = nt * 8 + t * 2;
                float2 uv = *(float2*)&su[c];
                float2 hv = *(float2*)&sh[c];
                float2 o0, o8;
                o0.x = st0.y * (acc[nt][0] - st0.x * uv.x) + hv.x;
                o0.y = st0.y * (acc[nt][1] - st0.x * uv.y) + hv.y;
                o8.x = st8.y * (acc[nt][2] - st8.x * uv.x) + hv.x;
                o8.y = st8.y * (acc[nt][3] - st8.x * uv.y) + hv.y;
                *(float2*)&out[ob0 + c] = o0;
                *(float2*)&out[ob8 + c] = o8;
            }
        }
        __syncthreads();   // all reads of this X buffer done before it is refilled
    }
}

// ============================ launch =========================================
extern "C" void kernel_launch(void* const* d_in, const int* in_sizes, int n_in,
                              void* d_out, int out_size) {
    const float* x    = (const float*)d_in[0];
    const float* ln_w = (const float*)d_in[1];
    const float* ln_b = (const float*)d_in[2];
    const float* Wl   = (const float*)d_in[3];
    const float* bl   = (const float*)d_in[4];
    const float* Wr   = (const float*)d_in[5];
    const float* br   = (const float*)d_in[6];
    const float* Wo   = (const float*)d_in[7];
    const float* bo   = (const float*)d_in[8];
    float* out = (float*)d_out;

    const int k3_smem = K3_SMEM_WORDS * (int)sizeof(uint32_t);
    cudaFuncSetAttribute(k3_mma, cudaFuncAttributeMaxDynamicSharedMemorySize, k3_smem);

    k1_stats<<<dim3(BLK1, BB), 256>>>(x);
    k2_fold<<<dim3(8, BB), 256>>>(ln_w, ln_b, Wl, bl, Wr, br, Wo, bo);
    k3_mma<<<dim3(NN / (NT * TILE), BB), 128, k3_smem>>>(x, out);
}

// round 11
// speedup vs baseline: 1.2247x; 1.0499x over previous
#include <cuda_runtime.h>
#include <math.h>
#include <stdint.h>

// Problem shape (fixed by the dataset)
#define BB 16
#define NN 8192
#define DD 128
#define HH 64
#define EE 64
#define EPS_LN 1e-5f

#define BLK1 64               // blocks per batch in pass 1
#define ROWS1 (NN / BLK1)     // 128 rows per pass-1 block
#define TILE 64               // rows per pass-3 block
#define XSP 132               // padded X smem row stride (words)

// ---------------- scratch (__device__ globals; no allocation allowed) -------
__device__ float  d_partial[BB][BLK1][DD];   // per-block col sums of (x-mu)*rstd
__device__ float2 d_stats[BB * NN];          // per-row {mu, rstd}
// G^T in mma-fragment-major order (tf32 bits):
// word addr = ((ks*4 + nt2)*32 + lane)*4 + comp, lane=g*4+t, comp=ntl*2+half
__device__ __align__(16) uint32_t d_Gf[BB][16 * 4 * 32 * 4];
__device__ float  d_u[BB][EE];               // u = (ln_w@Wr ⊙ lm) @ Wo
__device__ float  d_h[BB][EE];               // h = (ln_b@Wr ⊙ lm) @ Wo + c

__device__ __forceinline__ uint32_t smem_u32(const void* p) {
    uint32_t a;
    asm("{ .reg .u64 t; cvta.to.shared.u64 t, %1; cvt.u32.u64 %0, t; }" : "=r"(a) : "l"(p));
    return a;
}
__device__ __forceinline__ uint32_t f2tf32(float v) {
    uint32_t r;
    asm("cvt.rna.tf32.f32 %0, %1;" : "=r"(r) : "f"(v));
    return r;
}
__device__ __forceinline__ void cp16(uint32_t dst, const void* src) {
    asm volatile("cp.async.cg.shared.global [%0], [%1], 16;"
                 :: "r"(dst), "l"(src) : "memory");
}
__device__ __forceinline__ void mma_tf32(float* c, const uint32_t* a,
                                         uint32_t b0, uint32_t b1) {
    asm volatile(
        "mma.sync.aligned.m16n8k8.row.col.f32.tf32.tf32.f32 "
        "{%0,%1,%2,%3}, {%4,%5,%6,%7}, {%8,%9}, {%0,%1,%2,%3};"
        : "+f"(c[0]), "+f"(c[1]), "+f"(c[2]), "+f"(c[3])
        : "r"(a[0]), "r"(a[1]), "r"(a[2]), "r"(a[3]), "r"(b0), "r"(b1));
}

// ============================ Pass 1: row stats + column sums ===============
// (exact R7 configuration — measured best)
__global__ void k1_stats(const float* __restrict__ x) {
    int b    = blockIdx.y;
    int w    = threadIdx.x >> 5;
    int lane = threadIdx.x & 31;
    int rp   = lane >> 3;
    int c    = lane & 7;
    int rowbase = blockIdx.x * ROWS1 + w * (ROWS1 / 8);

    const float4* xb = (const float4*)(x + (size_t)b * NN * DD);

    float4 acc[4];
    #pragma unroll
    for (int j = 0; j < 4; j++) acc[j] = make_float4(0.f, 0.f, 0.f, 0.f);

    #pragma unroll
    for (int it = 0; it < 4; it++) {
        int row = rowbase + it * 4 + rp;
        float4 v[4];
        #pragma unroll
        for (int j = 0; j < 4; j++)
            v[j] = xb[row * (DD / 4) + (c + 8 * j)];
        float s = 0.f, q = 0.f;
        #pragma unroll
        for (int j = 0; j < 4; j++) {
            s += v[j].x + v[j].y + v[j].z + v[j].w;
            q += v[j].x * v[j].x + v[j].y * v[j].y + v[j].z * v[j].z + v[j].w * v[j].w;
        }
        #pragma unroll
        for (int o = 4; o > 0; o >>= 1) {
            s += __shfl_xor_sync(0xffffffffu, s, o);
            q += __shfl_xor_sync(0xffffffffu, q, o);
        }
        float mu   = s * (1.0f / DD);
        float rstd = rsqrtf(q * (1.0f / DD) - mu * mu + EPS_LN);
        if (c == 0) d_stats[b * NN + row] = make_float2(mu, rstd);
        #pragma unroll
        for (int j = 0; j < 4; j++) {
            acc[j].x += (v[j].x - mu) * rstd;
            acc[j].y += (v[j].y - mu) * rstd;
            acc[j].z += (v[j].z - mu) * rstd;
            acc[j].w += (v[j].w - mu) * rstd;
        }
    }

    __shared__ float sred[32][DD];
    {
        float4* dst = (float4*)sred[w * 4 + rp];
        #pragma unroll
        for (int j = 0; j < 4; j++) dst[c + 8 * j] = acc[j];
    }
    __syncthreads();
    if (threadIdx.x < DD) {
        float s = 0.f;
        #pragma unroll
        for (int k = 0; k < 32; k++) s += sred[k][threadIdx.x];
        d_partial[b][blockIdx.x][threadIdx.x] = s;
    }
}

// ============================ Pass 2: fold (one kernel, 128 blocks) ==========
__global__ void __launch_bounds__(256) k2_fold(
    const float* __restrict__ ln_w, const float* __restrict__ ln_b,
    const float* __restrict__ Wl,   const float* __restrict__ bl,
    const float* __restrict__ Wr,   const float* __restrict__ br,
    const float* __restrict__ Wo,   const float* __restrict__ bo) {
    __shared__ float sxa[2][DD];
    __shared__ float sx[DD];
    __shared__ float sr4[4][HH];
    __shared__ float slm[HH];
    __shared__ float sP[HH * EE];
    __shared__ float sWr[16 * HH];
    __shared__ float swv4[4][HH], sbv4[4][HH];

    int b = blockIdx.y, bx = blockIdx.x, tid = threadIdx.x;
    int d0 = bx * 16;

    {
        int col = tid & 127, hf = tid >> 7;
        float s = 0.f;
        #pragma unroll 8
        for (int p = hf * 32; p < hf * 32 + 32; p++) s += d_partial[b][p][col];
        sxa[hf][col] = s;
    }
    #pragma unroll
    for (int i = tid; i < 16 * HH; i += 256)
        sWr[i] = Wr[(d0 + (i >> 6)) * HH + (i & 63)];
    __syncthreads();
    if (tid < DD)
        sx[tid] = ln_w[tid] * ((sxa[0][tid] + sxa[1][tid]) * (1.0f / NN)) + ln_b[tid];
    __syncthreads();

    {
        int h = tid & 63, q = tid >> 6;
        float a = 0.f;
        #pragma unroll 8
        for (int d = q * 32; d < q * 32 + 32; d++) a += sx[d] * Wl[d * HH + h];
        sr4[q][h] = a;
    }
    __syncthreads();
    if (tid < HH)
        slm[tid] = bl[tid] + sr4[0][tid] + sr4[1][tid] + sr4[2][tid] + sr4[3][tid];
    __syncthreads();

    #pragma unroll
    for (int i = tid; i < HH * EE; i += 256) sP[i] = slm[i >> 6] * Wo[i];
    __syncthreads();

    // G rows -> fragment-major tf32 into d_Gf
    {
        int d_l = tid >> 4, e0 = (tid & 15) * 4;
        float a0 = 0.f, a1 = 0.f, a2 = 0.f, a3 = 0.f;
        #pragma unroll 8
        for (int h = 0; h < HH; h++) {
            float wv = sWr[d_l * HH + h];
            const float* p = &sP[h * EE + e0];
            a0 += wv * p[0]; a1 += wv * p[1]; a2 += wv * p[2]; a3 += wv * p[3];
        }
        int d = d0 + d_l;
        float lw = ln_w[d];
        float gv[4] = { lw * a0, lw * a1, lw * a2, lw * a3 };
        int ks = d >> 3, t = d & 3, half = (d >> 2) & 1;
        uint32_t* gf = d_Gf[b];
        #pragma unroll
        for (int j = 0; j < 4; j++) {
            int e = e0 + j;
            int g = e & 7, nt2 = e >> 4, ntl = (e >> 3) & 1;
            int laneix = g * 4 + t;
            int addr = ((ks * 4 + nt2) * 32 + laneix) * 4 + (ntl * 2 + half);
            gf[addr] = f2tf32(gv[j]);
        }
    }

    if (bx == 0) {
        {
            int h = tid & 63, q = tid >> 6;
            float aw = 0.f, ab = 0.f;
            #pragma unroll 8
            for (int d = q * 32; d < q * 32 + 32; d++) {
                float wr = Wr[d * HH + h];
                aw += ln_w[d] * wr;
                ab += ln_b[d] * wr;
            }
            swv4[q][h] = aw; sbv4[q][h] = ab;
        }
        __syncthreads();
        if (tid < EE) {
            int e = tid;
            float su = 0.f, sh = 0.f, sc = bo[e];
            #pragma unroll 8
            for (int h = 0; h < HH; h++) {
                float p  = sP[h * EE + e];
                float wv = swv4[0][h] + swv4[1][h] + swv4[2][h] + swv4[3][h];
                float bv = sbv4[0][h] + sbv4[1][h] + sbv4[2][h] + sbv4[3][h];
                su += wv * p;
                sh += bv * p;
                sc += br[h] * p;
            }
            d_u[b][e] = su;
            d_h[b][e] = sh + sc;
        }
    }
}

// ============================ Pass 3: mma.sync tf32 GEMM =====================
// D[64,64] = X_tile[64,128] @ G[128,64]; epilogue rstd*(D - mu*u) + h.
// 128 threads / 4 warps; warp w owns rows [16w, 16w+16), all 64 cols.
// Gf fragment-major: B fragments load as 4 LDS.128 per k-step.
#define GF_WORDS (16 * 4 * 32 * 4)
#define K3_SMEM_WORDS (GF_WORDS + TILE * XSP + EE + EE + 2 * TILE)

__global__ void __launch_bounds__(128, 3) k3_mma(const float* __restrict__ x,
                                                 float* __restrict__ out) {
    extern __shared__ uint32_t sm[];
    uint32_t* Gf  = sm;                        // [16][4][32] uint4 fragment-major
    uint32_t* Xs  = Gf + GF_WORDS;             // [TILE][XSP] raw fp32 bits
    float*    su  = (float*)(Xs + TILE * XSP); // [EE]
    float*    sh  = su + EE;                   // [EE]
    float2*   sst = (float2*)(sh + EE);        // [TILE]

    int b    = blockIdx.y;
    int tid  = threadIdx.x;
    int w    = tid >> 5, lane = tid & 31;
    int g    = lane >> 2, t = lane & 3;
    int row0 = blockIdx.x * TILE;

    // ---- stage Gf + X via cp.async ----
    {
        const char* gsrc = (const char*)d_Gf[b];
        #pragma unroll
        for (int i = 0; i < 16; i++) {
            int fid = tid + i * 128;           // 2048 16B chunks
            cp16(smem_u32(&Gf[fid * 4]), gsrc + (size_t)fid * 16);
        }
        const char* xsrc = (const char*)(x + ((size_t)b * NN + row0) * DD);
        #pragma unroll
        for (int i = 0; i < 16; i++) {
            int fid = tid + i * 128;           // 2048 chunks (64 rows x 128)
            int r = fid >> 5, cq = fid & 31;
            cp16(smem_u32(&Xs[r * XSP + 4 * cq]), xsrc + (size_t)fid * 16);
        }
        asm volatile("cp.async.commit_group;" ::: "memory");
    }
    if (tid < EE) { su[tid] = d_u[b][tid]; sh[tid] = d_h[b][tid]; }
    if (tid < TILE) sst[tid] = d_stats[b * NN + row0 + tid];
    asm volatile("cp.async.wait_group 0;" ::: "memory");
    __syncthreads();

    // ---- mainloop: 16 k-steps; A = 4 LDS.32 + cvt, B = 4 LDS.128 ----
    float acc[8][4];
    #pragma unroll
    for (int nt = 0; nt < 8; nt++)
        #pragma unroll
        for (int j = 0; j < 4; j++) acc[nt][j] = 0.f;

    int rA0 = w * 16 + g;
    #pragma unroll
    for (int ks = 0; ks < 16; ks++) {
        int k0 = ks * 8;
        uint32_t a[4];
        {
            const uint32_t* xr = &Xs[rA0 * XSP + k0 + t];
            a[0] = f2tf32(__uint_as_float(xr[0]));
            a[1] = f2tf32(__uint_as_float(xr[8 * XSP]));
            a[2] = f2tf32(__uint_as_float(xr[4]));
            a[3] = f2tf32(__uint_as_float(xr[8 * XSP + 4]));
        }
        const uint4* gfk = (const uint4*)&Gf[(ks * 4) * 32 * 4];
        #pragma unroll
        for (int nt2 = 0; nt2 < 4; nt2++) {
            uint4 q = gfk[nt2 * 32 + lane];
            mma_tf32(acc[nt2 * 2 + 0], a, q.x, q.y);
            mma_tf32(acc[nt2 * 2 + 1], a, q.z, q.w);
        }
    }

    // ---- epilogue: out = rstd*(acc - mu*u) + h ----
    {
        int rl = w * 16 + g;                   // local rows rl, rl+8
        float2 st0 = sst[rl];
        float2 st8 = sst[rl + 8];
        size_t ob0 = ((size_t)b * NN + row0 + rl) * EE;
        size_t ob8 = ob0 + 8 * EE;
        #pragma unroll
        for (int nt = 0; nt < 8; nt++) {
            int c = nt * 8 + t * 2;
            float2 uv = *(float2*)&su[c];
            float2 hv = *(float2*)&sh[c];
            float2 o0, o8;
            o0.x = st0.y * (acc[nt][0] - st0.x * uv.x) + hv.x;
            o0.y = st0.y * (acc[nt][1] - st0.x * uv.y) + hv.y;
            o8.x = st8.y * (acc[nt][2] - st8.x * uv.x) + hv.x;
            o8.y = st8.y * (acc[nt][3] - st8.x * uv.y) + hv.y;
            *(float2*)&out[ob0 + c] = o0;
            *(float2*)&out[ob8 + c] = o8;
        }
    }
}

// ============================ launch =========================================
extern "C" void kernel_launch(void* const* d_in, const int* in_sizes, int n_in,
                              void* d_out, int out_size) {
    const float* x    = (const float*)d_in[0];
    const float* ln_w = (const float*)d_in[1];
    const float* ln_b = (const float*)d_in[2];
    const float* Wl   = (const float*)d_in[3];
    const float* bl   = (const float*)d_in[4];
    const float* Wr   = (const float*)d_in[5];
    const float* br   = (const float*)d_in[6];
    const float* Wo   = (const float*)d_in[7];
    const float* bo   = (const float*)d_in[8];
    float* out = (float*)d_out;

    const int k3_smem = K3_SMEM_WORDS * (int)sizeof(uint32_t);
    cudaFuncSetAttribute(k3_mma, cudaFuncAttributeMaxDynamicSharedMemorySize, k3_smem);

    k1_stats<<<dim3(BLK1, BB), 256>>>(x);
    k2_fold<<<dim3(8, BB), 256>>>(ln_w, ln_b, Wl, bl, Wr, br, Wo, bo);
    k3_mma<<<dim3(NN / TILE, BB), 128, k3_smem>>>(x, out);
}